// round 14
// baseline (speedup 1.0000x reference)
#include <cuda_runtime.h>
#include <cuda_bf16.h>
#include <cstdint>

// Problem constants
#define BATCH 4
#define CH    128
#define HW    64
#define PQ    4096            // HW*HW
#define SCALE 10.0f
#define EPS_SUM 0.1152f       // 128*3*3*1e-4
#define LOG2E 1.4426950408889634f
#define KTOT  384             // split-bf16 packed K (ah|al|ah vs bh|bh|bl)
#define BKP   32              // bf16 K per pipeline stage
#define NKIT  (KTOT / BKP)    // 12 stages
#define LDT   40              // padded smem row length (bf16)
// GEMM CTA tile: 256 (m) x 128 (n); stage holds A[256][32] + B[128][32]
#define BM    256
#define BN    128
#define BREG_OFF    (BM * LDT * 2)              // B region within a stage = 20480 B
#define STAGE_BYTES ((BM + BN) * LDT * 2)       // 30720 B
#define NSTAGE 3
#define GEMM_SMEM (NSTAGE * STAGE_BYTES)        // 92160 B

// ---------------- static scratch ----------------
__device__ float g_G[(size_t)BATCH * PQ * PQ];   // Gt[b][p][q]  (256 MB)
__device__ float g_ssq[BATCH * PQ];
__device__ float g_coef[BATCH * PQ];
__device__ float g_mm[PQ];
__device__ float g_partial[BATCH * 64 * PQ];
__device__ float g_colsum[BATCH * PQ];
// tile-contiguous pack: [b][kk][p][32] ; chunk kk holds k = kk*32..kk*32+31
__device__ __nv_bfloat16 g_Apack[(size_t)BATCH * NKIT * PQ * 32];
__device__ __nv_bfloat16 g_Bpack[(size_t)BATCH * NKIT * PQ * 32];

// ---------------- helpers ----------------
__device__ __forceinline__ uint32_t smem_u32(const void* p) {
    uint32_t a;
    asm("{ .reg .u64 t; cvta.to.shared.u64 t, %1; cvt.u32.u64 %0, t; }" : "=r"(a) : "l"(p));
    return a;
}
__device__ __forceinline__ void cpa16s(uint32_t dst, const void* src) {
    asm volatile("cp.async.cg.shared.global [%0], [%1], 16;" :: "r"(dst), "l"(src));
}
#define CP_COMMIT() asm volatile("cp.async.commit_group;" ::: "memory")
#define CP_WAIT(n)  asm volatile("cp.async.wait_group %0;" :: "n"(n) : "memory")

__device__ __forceinline__ void ldsm_x4(uint32_t* r, uint32_t addr) {
    asm volatile("ldmatrix.sync.aligned.m8n8.x4.shared.b16 {%0,%1,%2,%3}, [%4];"
                 : "=r"(r[0]), "=r"(r[1]), "=r"(r[2]), "=r"(r[3]) : "r"(addr));
}
__device__ __forceinline__ void mma16816(float* c, const uint32_t* a, const uint32_t* bfr) {
    asm volatile(
        "mma.sync.aligned.m16n8k16.row.col.f32.bf16.bf16.f32 "
        "{%0,%1,%2,%3}, {%4,%5,%6,%7}, {%8,%9}, {%0,%1,%2,%3};"
        : "+f"(c[0]), "+f"(c[1]), "+f"(c[2]), "+f"(c[3])
        : "r"(a[0]), "r"(a[1]), "r"(a[2]), "r"(a[3]), "r"(bfr[0]), "r"(bfr[1]));
}

// fast 2^t on the FMA pipe (degree-5, rel err ~2.4e-6)
__device__ __forceinline__ float fast_exp2(float t) {
    t = fminf(fmaxf(t, -120.0f), 120.0f);
    float fn = rintf(t);
    float f  = t - fn;
    float p  = 1.3333558e-3f;
    p = fmaf(p, f, 9.6181291e-3f);
    p = fmaf(p, f, 5.5504109e-2f);
    p = fmaf(p, f, 2.4022651e-1f);
    p = fmaf(p, f, 6.9314718e-1f);
    p = fmaf(p, f, 1.0f);
    int n = (int)fn;
    return p * __int_as_float((n + 127) << 23);
}

// ---------------- K-1: split fp32 -> packed bf16 hi/lo (tile-contiguous) ------------
__global__ void k_split(const float* __restrict__ fin, const float* __restrict__ bin) {
    __shared__ float tile[32][33];
    int z = blockIdx.z;
    int isA = (z < BATCH);
    int b = isA ? z : z - BATCH;
    const float* src = (isA ? bin : fin) + (size_t)b * CH * PQ;
    __nv_bfloat16* dst = (isA ? g_Apack : g_Bpack) + (size_t)b * NKIT * PQ * 32;

    int p0 = blockIdx.x * 32, c0 = blockIdx.y * 32;
    int kk0 = c0 >> 5;                       // hi chunk index; mid = +4, far = +8
    int tx = threadIdx.x, ty = threadIdx.y;  // (32, 8)
#pragma unroll
    for (int j = 0; j < 4; j++)
        tile[ty + 8 * j][tx] = src[(size_t)(c0 + ty + 8 * j) * PQ + p0 + tx];
    __syncthreads();
    const size_t CHK = (size_t)PQ * 32;      // elements per kk chunk
#pragma unroll
    for (int j = 0; j < 4; j++) {
        int r = ty + 8 * j;
        float a = tile[tx][r];               // channel c0+tx, pixel p0+r
        __nv_bfloat16 hi = __float2bfloat16_rn(a);
        __nv_bfloat16 lo = __float2bfloat16_rn(a - __bfloat162float(hi));
        size_t poff = (size_t)(p0 + r) * 32 + tx;
        dst[(size_t)kk0 * CHK + poff]        = hi;
        dst[(size_t)(kk0 + 4) * CHK + poff]  = isA ? lo : hi;
        dst[(size_t)(kk0 + 8) * CHK + poff]  = isA ? hi : lo;
    }
}

// ---------------- K0a: ssq[b,p] = sum_c b[b,c,p]^2 ----------------
__global__ void k_ssq(const float* __restrict__ bin) {
    int p = blockIdx.x * 256 + threadIdx.x;
    int b = blockIdx.y;
    const float* src = bin + ((size_t)b * CH) * PQ + p;
    float s = 0.f;
#pragma unroll 8
    for (int c = 0; c < CH; c++) {
        float v = src[(size_t)c * PQ];
        s += v * v;
    }
    g_ssq[b * PQ + p] = s;
}

// ---------------- K0b: coef ----------------
__global__ void k_prep(const float* __restrict__ mask) {
    int p = blockIdx.x * 256 + threadIdx.x;
    int b = blockIdx.y;
    int py = p >> 6, px = p & 63;

    float s = EPS_SUM;
    bool masked = false;
#pragma unroll
    for (int dy = -1; dy <= 1; dy++) {
#pragma unroll
        for (int dx = -1; dx <= 1; dx++) {
            int yy = py + dy, xx = px + dx;
            if ((unsigned)yy < 64u && (unsigned)xx < 64u) {
                s += g_ssq[b * PQ + (yy << 6) + xx];
                if (mask[(size_t)(yy * 8) * 512 + xx * 8] != 0.0f) masked = true;
            }
        }
    }
    g_coef[b * PQ + p] = masked ? 0.0f : (SCALE * LOG2E / sqrtf(s));
    if (b == 0) g_mm[p] = masked ? 0.0f : 1.0f;
}

// ---------------- K1: HMMA bf16-split GEMM  Gt[p][q] = A.B ----------------
// CTA 256x128, K=384, BK=32, 256 thr = 8 warps (4 m x 2 n), warp tile 64x64.
// 3-stage cp.async pipeline, dynamic smem (92KB), 1 CTA/SM.
__global__ __launch_bounds__(256, 1) void k_gemm_mma() {
    extern __shared__ __align__(16) char smem[];
    uint32_t sbase = smem_u32(smem);

    int tid = threadIdx.x;
    int wid = tid >> 5, lid = tid & 31;
    int g = lid >> 2, tig = lid & 3;
    int warp_m = wid & 3, warp_n = wid >> 2;

    int b  = blockIdx.z;
    int m0 = blockIdx.y * BM;   // p
    int n0 = blockIdx.x * BN;   // q
    const size_t CHK = (size_t)PQ * 32;
    const __nv_bfloat16* Ap = g_Apack + (size_t)b * NKIT * CHK + (size_t)m0 * 32;
    const __nv_bfloat16* Bp = g_Bpack + (size_t)b * NKIT * CHK + (size_t)n0 * 32;

    float acc[4][8][4];
#pragma unroll
    for (int mt = 0; mt < 4; mt++)
#pragma unroll
        for (int nt = 0; nt < 8; nt++)
#pragma unroll
            for (int i = 0; i < 4; i++) acc[mt][nt][i] = 0.f;

    // ldmatrix per-lane byte offsets within a stage
    uint32_t a_off[4];
#pragma unroll
    for (int mt = 0; mt < 4; mt++) {
        int row = warp_m * 64 + mt * 16 + (lid & 15);
        int kof = (lid >> 4) * 8;
        a_off[mt] = (uint32_t)((row * LDT + kof) * 2);
    }
    uint32_t b_off[4];
#pragma unroll
    for (int ntp = 0; ntp < 4; ntp++) {
        int row = warp_n * 64 + ntp * 16 + (lid & 7) + ((lid >> 4) << 3);
        int kof = ((lid >> 3) & 1) * 8;
        b_off[ntp] = (uint32_t)(BREG_OFF + (row * LDT + kof) * 2);
    }

    // dense stage fill: A = 1024 x 16B chunks, B = 512 x 16B chunks, 256 threads
    // A: 4 chunks/thread, B: 2 chunks/thread; gmem fully contiguous per stage.
#define FILL_STAGE(sb, Asrc, Bsrc)                                                   \
    do {                                                                             \
        _Pragma("unroll")                                                            \
        for (int i = 0; i < 4; i++) {                                                \
            int ci = tid + i * 256;                                                  \
            cpa16s((sb) + (ci >> 2) * (LDT * 2) + (ci & 3) * 16, (Asrc) + (size_t)ci * 8); \
        }                                                                            \
        _Pragma("unroll")                                                            \
        for (int i = 0; i < 2; i++) {                                                \
            int ci = tid + i * 256;                                                  \
            cpa16s((sb) + BREG_OFF + (ci >> 2) * (LDT * 2) + (ci & 3) * 16, (Bsrc) + (size_t)ci * 8); \
        }                                                                            \
    } while (0)

    // prologue: stages 0 and 1 (two commit groups)
    FILL_STAGE(sbase, Ap, Bp);
    CP_COMMIT();
    FILL_STAGE(sbase + STAGE_BYTES, Ap + CHK, Bp + CHK);
    CP_COMMIT();

    int bufR = 0, bufW = 2;
#pragma unroll 1
    for (int kk = 0; kk < NKIT; kk++) {
        CP_WAIT(1);          // stage kk resident
        __syncthreads();     // all warps done reading the buffer bufW will overwrite
        if (kk + 2 < NKIT) {
            FILL_STAGE(sbase + (uint32_t)bufW * STAGE_BYTES,
                       Ap + (size_t)(kk + 2) * CHK, Bp + (size_t)(kk + 2) * CHK);
            CP_COMMIT();
        }
        uint32_t stg = sbase + (uint32_t)bufR * STAGE_BYTES;
#pragma unroll
        for (int ks = 0; ks < 2; ks++) {
            uint32_t kadj = (uint32_t)(ks * 32);   // 16 bf16 = 32 B
            uint32_t afr[4][4];
#pragma unroll
            for (int mt = 0; mt < 4; mt++) ldsm_x4(afr[mt], stg + a_off[mt] + kadj);
            uint32_t bfr[4][4];
#pragma unroll
            for (int ntp = 0; ntp < 4; ntp++) ldsm_x4(bfr[ntp], stg + b_off[ntp] + kadj);
#pragma unroll
            for (int mt = 0; mt < 4; mt++)
#pragma unroll
                for (int nt = 0; nt < 8; nt++)
                    mma16816(acc[mt][nt], afr[mt], &bfr[nt >> 1][(nt & 1) * 2]);
        }
        bufR = (bufR == NSTAGE - 1) ? 0 : bufR + 1;
        bufW = (bufW == NSTAGE - 1) ? 0 : bufW + 1;
    }

    // epilogue: static-indexed float2 stores (no dynamic acc indexing -> no spills)
    float* Gp = g_G + (size_t)b * PQ * PQ;
#pragma unroll
    for (int mt = 0; mt < 4; mt++) {
        int row = m0 + warp_m * 64 + mt * 16 + g;
#pragma unroll
        for (int nt = 0; nt < 8; nt++) {
            int col = n0 + warp_n * 64 + nt * 8 + tig * 2;
            *(float2*)&Gp[(size_t)row * PQ + col]       = make_float2(acc[mt][nt][0], acc[mt][nt][1]);
            *(float2*)&Gp[(size_t)(row + 8) * PQ + col] = make_float2(acc[mt][nt][2], acc[mt][nt][3]);
        }
    }
}

// ---------------- K2: 9-tap diagonal sum + exp2 + out + column partials ----------------
__global__ __launch_bounds__(256) void k_sum9(float* __restrict__ out) {
    int b    = blockIdx.z;
    int prow = blockIdx.y;
    int q    = blockIdx.x * 256 + threadIdx.x;
    int qy   = q >> 6, qx = q & 63;

    const float* __restrict__ Gp = g_G + (size_t)b * PQ * PQ;
    const float* __restrict__ cf = g_coef + b * PQ + prow * 64;

    const bool rvm = (prow > 0)  && (qy > 0);
    const bool rvp = (prow < 63) && (qy < 63);
    const bool qlf = (qx > 0), qrt = (qx < 63);

    const float* base = Gp + (size_t)(prow * 64) * PQ + q;
    float* orow = out + ((size_t)(b * PQ + prow * 64)) * PQ + q;
    float partial = 0.f;

#pragma unroll 8
    for (int px = 0; px < 64; px++) {
        bool lf = qlf && (px > 0);
        bool rt = qrt && (px < 63);
        float s = 0.f;
        if (rvm) {
            if (lf) s += __ldg(base - 65 * 4097);
            s += __ldg(base - 64 * 4097);
            if (rt) s += __ldg(base - 63 * 4097);
        }
        if (lf) s += __ldg(base - 4097);
        s += __ldg(base);
        if (rt) s += __ldg(base + 4097);
        if (rvp) {
            if (lf) s += __ldg(base + 63 * 4097);
            s += __ldg(base + 64 * 4097);
            if (rt) s += __ldg(base + 65 * 4097);
        }
        float e = fast_exp2(s * cf[px]);
        __stcs(orow, e);
        partial += e;
        base += PQ;
        orow += PQ;
    }
    g_partial[((size_t)(b * 64 + prow)) * PQ + q] = partial;
}

// ---------------- K2b: deterministic reduction of column partials ----------------
__global__ void k_colreduce() {
    int q = blockIdx.x * 256 + threadIdx.x;
    int b = blockIdx.y;
    const float* src = g_partial + (size_t)(b * 64) * PQ + q;
    float s = 0.f;
#pragma unroll 8
    for (int j = 0; j < 64; j++) s += src[(size_t)j * PQ];
    g_colsum[b * PQ + q] = s;
}

// ---------------- K3: normalize ----------------
__global__ void k_norm(float* __restrict__ out) {
    size_t i4  = (size_t)blockIdx.x * 256 + threadIdx.x;
    size_t row = i4 >> 10;
    int p  = (int)(row & 4095);
    int b  = (int)(row >> 12);
    int c4 = (int)(i4 & 1023);

    float4 v  = __ldcs((const float4*)out + i4);
    float  m  = g_mm[p];
    float4 cs = ((const float4*)g_colsum)[b * 1024 + c4];
    v.x = m * v.x / cs.x;
    v.y = m * v.y / cs.y;
    v.z = m * v.z / cs.z;
    v.w = m * v.w / cs.w;
    __stcs((float4*)out + i4, v);
}

// ---------------- launch ----------------
extern "C" void kernel_launch(void* const* d_in, const int* in_sizes, int n_in,
                              void* d_out, int out_size) {
    const float* f    = (const float*)d_in[0];
    const float* bb   = (const float*)d_in[1];
    const float* mask = (const float*)d_in[2];
    float* out = (float*)d_out;

    cudaFuncSetAttribute(k_gemm_mma, cudaFuncAttributeMaxDynamicSharedMemorySize, GEMM_SMEM);

    k_split    <<<dim3(PQ / 32, CH / 32, 2 * BATCH), dim3(32, 8)>>>(f, bb);
    k_ssq      <<<dim3(PQ / 256, BATCH), 256>>>(bb);
    k_prep     <<<dim3(PQ / 256, BATCH), 256>>>(mask);
    k_gemm_mma <<<dim3(PQ / BN, PQ / BM, BATCH), 256, GEMM_SMEM>>>();
    k_sum9     <<<dim3(PQ / 256, 64, BATCH), 256>>>(out);
    k_colreduce<<<dim3(PQ / 256, BATCH), 256>>>();
    k_norm     <<<(unsigned)(((size_t)BATCH * PQ * PQ / 4) / 256), 256>>>(out);
}

// round 15
// speedup vs baseline: 1.0244x; 1.0244x over previous
#include <cuda_runtime.h>
#include <cuda_bf16.h>
#include <cstdint>

// Problem constants
#define BATCH 4
#define CH    128
#define HW    64
#define PQ    4096            // HW*HW
#define SCALE 10.0f
#define EPS_SUM 0.1152f       // 128*3*3*1e-4
#define LOG2E 1.4426950408889634f
#define KTOT  384             // split-bf16 packed K (ah|al|ah vs bh|bh|bl)
#define BKP   32              // bf16 K per pipeline stage
#define NKIT  (KTOT / BKP)    // 12 stages
#define LDT   40              // padded smem row length (bf16)
#define STAGE_BYTES (2 * 128 * LDT * 2)   // one stage (A+B)  = 20480 B
#define BREG_OFF    (128 * LDT * 2)       // B region within a stage = 10240 B

// ---------------- static scratch ----------------
__device__ float g_G[(size_t)BATCH * PQ * PQ];   // Gt[b][p][q]  (256 MB)
__device__ float g_ssq[BATCH * PQ];
__device__ float g_coef[BATCH * PQ];
__device__ float g_mm[PQ];
__device__ float g_partial[BATCH * 64 * PQ];
__device__ float g_colsum[BATCH * PQ];
// tile-contiguous pack: [b][kk][p][32] ; chunk kk holds k = kk*32..kk*32+31
__device__ __nv_bfloat16 g_Apack[(size_t)BATCH * NKIT * PQ * 32];
__device__ __nv_bfloat16 g_Bpack[(size_t)BATCH * NKIT * PQ * 32];

// ---------------- helpers ----------------
__device__ __forceinline__ uint32_t smem_u32(const void* p) {
    uint32_t a;
    asm("{ .reg .u64 t; cvta.to.shared.u64 t, %1; cvt.u32.u64 %0, t; }" : "=r"(a) : "l"(p));
    return a;
}
__device__ __forceinline__ void cpa16(void* dst, const void* src) {
    asm volatile("cp.async.cg.shared.global [%0], [%1], 16;"
                 :: "r"(smem_u32(dst)), "l"(src));
}
#define CP_COMMIT() asm volatile("cp.async.commit_group;" ::: "memory")
#define CP_WAIT(n)  asm volatile("cp.async.wait_group %0;" :: "n"(n) : "memory")

__device__ __forceinline__ void ldsm_x4(uint32_t* r, uint32_t addr) {
    asm volatile("ldmatrix.sync.aligned.m8n8.x4.shared.b16 {%0,%1,%2,%3}, [%4];"
                 : "=r"(r[0]), "=r"(r[1]), "=r"(r[2]), "=r"(r[3]) : "r"(addr));
}
__device__ __forceinline__ void mma16816(float* c, const uint32_t* a, const uint32_t* bfr) {
    asm volatile(
        "mma.sync.aligned.m16n8k16.row.col.f32.bf16.bf16.f32 "
        "{%0,%1,%2,%3}, {%4,%5,%6,%7}, {%8,%9}, {%0,%1,%2,%3};"
        : "+f"(c[0]), "+f"(c[1]), "+f"(c[2]), "+f"(c[3])
        : "r"(a[0]), "r"(a[1]), "r"(a[2]), "r"(a[3]), "r"(bfr[0]), "r"(bfr[1]));
}

// fast 2^t on the FMA pipe (degree-5, rel err ~2.4e-6)
__device__ __forceinline__ float fast_exp2(float t) {
    t = fminf(fmaxf(t, -120.0f), 120.0f);
    float fn = rintf(t);
    float f  = t - fn;
    float p  = 1.3333558e-3f;
    p = fmaf(p, f, 9.6181291e-3f);
    p = fmaf(p, f, 5.5504109e-2f);
    p = fmaf(p, f, 2.4022651e-1f);
    p = fmaf(p, f, 6.9314718e-1f);
    p = fmaf(p, f, 1.0f);
    int n = (int)fn;
    return p * __int_as_float((n + 127) << 23);
}

// ---------------- K-1: split fp32 -> packed bf16 hi/lo (tile-contiguous) ------------
__global__ void k_split(const float* __restrict__ fin, const float* __restrict__ bin) {
    __shared__ float tile[32][33];
    int z = blockIdx.z;
    int isA = (z < BATCH);
    int b = isA ? z : z - BATCH;
    const float* src = (isA ? bin : fin) + (size_t)b * CH * PQ;
    __nv_bfloat16* dst = (isA ? g_Apack : g_Bpack) + (size_t)b * NKIT * PQ * 32;

    int p0 = blockIdx.x * 32, c0 = blockIdx.y * 32;
    int kk0 = c0 >> 5;                       // hi chunk index; mid = +4, far = +8
    int tx = threadIdx.x, ty = threadIdx.y;  // (32, 8)
#pragma unroll
    for (int j = 0; j < 4; j++)
        tile[ty + 8 * j][tx] = src[(size_t)(c0 + ty + 8 * j) * PQ + p0 + tx];
    __syncthreads();
    const size_t CHK = (size_t)PQ * 32;      // elements per kk chunk
#pragma unroll
    for (int j = 0; j < 4; j++) {
        int r = ty + 8 * j;
        float a = tile[tx][r];               // channel c0+tx, pixel p0+r
        __nv_bfloat16 hi = __float2bfloat16_rn(a);
        __nv_bfloat16 lo = __float2bfloat16_rn(a - __bfloat162float(hi));
        size_t poff = (size_t)(p0 + r) * 32 + tx;
        dst[(size_t)kk0 * CHK + poff]        = hi;
        dst[(size_t)(kk0 + 4) * CHK + poff]  = isA ? lo : hi;
        dst[(size_t)(kk0 + 8) * CHK + poff]  = isA ? hi : lo;
    }
}

// ---------------- K0a: ssq[b,p] = sum_c b[b,c,p]^2 ----------------
__global__ void k_ssq(const float* __restrict__ bin) {
    int p = blockIdx.x * 256 + threadIdx.x;
    int b = blockIdx.y;
    const float* src = bin + ((size_t)b * CH) * PQ + p;
    float s = 0.f;
#pragma unroll 8
    for (int c = 0; c < CH; c++) {
        float v = src[(size_t)c * PQ];
        s += v * v;
    }
    g_ssq[b * PQ + p] = s;
}

// ---------------- K0b: coef ----------------
__global__ void k_prep(const float* __restrict__ mask) {
    int p = blockIdx.x * 256 + threadIdx.x;
    int b = blockIdx.y;
    int py = p >> 6, px = p & 63;

    float s = EPS_SUM;
    bool masked = false;
#pragma unroll
    for (int dy = -1; dy <= 1; dy++) {
#pragma unroll
        for (int dx = -1; dx <= 1; dx++) {
            int yy = py + dy, xx = px + dx;
            if ((unsigned)yy < 64u && (unsigned)xx < 64u) {
                s += g_ssq[b * PQ + (yy << 6) + xx];
                if (mask[(size_t)(yy * 8) * 512 + xx * 8] != 0.0f) masked = true;
            }
        }
    }
    g_coef[b * PQ + p] = masked ? 0.0f : (SCALE * LOG2E / sqrtf(s));
    if (b == 0) g_mm[p] = masked ? 0.0f : 1.0f;
}

// ---------------- K1: HMMA bf16-split GEMM  Gt[p][q] = A.B (64x64 warp tile) -------
// CTA 128x128, K=384, BK=32, 128 thr = 4 warps (2 m x 2 n), warp tile 64x64.
// Tile-contiguous pack -> dense 8KB stage fills; static-indexed float2 epilogue.
__global__ __launch_bounds__(128, 2) void k_gemm_mma(int b) {
    __shared__ __align__(16) __nv_bfloat16 sm[2][2][128][LDT];  // [stage][A/B][row][k]
    uint32_t sbase = smem_u32(&sm[0][0][0][0]);

    int tid = threadIdx.x;
    int wid = tid >> 5, lid = tid & 31;
    int g = lid >> 2, tig = lid & 3;
    int warp_m = wid & 1, warp_n = wid >> 1;

    int m0 = blockIdx.y * 128;   // p
    int n0 = blockIdx.x * 128;   // q
    const size_t CHK = (size_t)PQ * 32;
    const __nv_bfloat16* Ap = g_Apack + (size_t)b * NKIT * CHK + (size_t)m0 * 32;
    const __nv_bfloat16* Bp = g_Bpack + (size_t)b * NKIT * CHK + (size_t)n0 * 32;

    float acc[4][8][4];
#pragma unroll
    for (int mt = 0; mt < 4; mt++)
#pragma unroll
        for (int nt = 0; nt < 8; nt++)
#pragma unroll
            for (int i = 0; i < 4; i++) acc[mt][nt][i] = 0.f;

    // ldmatrix per-lane byte offsets within a stage
    uint32_t a_off[4];
#pragma unroll
    for (int mt = 0; mt < 4; mt++) {
        int row = warp_m * 64 + mt * 16 + (lid & 15);
        int kof = (lid >> 4) * 8;
        a_off[mt] = (uint32_t)((row * LDT + kof) * 2);
    }
    uint32_t b_off[4];
#pragma unroll
    for (int ntp = 0; ntp < 4; ntp++) {
        int row = warp_n * 64 + ntp * 16 + (lid & 7) + ((lid >> 4) << 3);
        int kof = ((lid >> 3) & 1) * 8;
        b_off[ntp] = (uint32_t)(BREG_OFF + (row * LDT + kof) * 2);
    }

    // dense stage fill: 512 x 16B chunks per operand; thread handles ci = tid + i*128
#pragma unroll
    for (int i = 0; i < 4; i++) {
        int ci = tid + i * 128;
        cpa16((char*)&sm[0][0][0][0] + (ci >> 2) * (LDT * 2) + (ci & 3) * 16, Ap + (size_t)ci * 8);
        cpa16((char*)&sm[0][1][0][0] + (ci >> 2) * (LDT * 2) + (ci & 3) * 16, Bp + (size_t)ci * 8);
    }
    CP_COMMIT();

#pragma unroll 1
    for (int kk = 0; kk < NKIT; kk++) {
        if (kk + 1 < NKIT) {
            int st = (kk + 1) & 1;
            const __nv_bfloat16* An = Ap + (size_t)(kk + 1) * CHK;
            const __nv_bfloat16* Bn = Bp + (size_t)(kk + 1) * CHK;
#pragma unroll
            for (int i = 0; i < 4; i++) {
                int ci = tid + i * 128;
                cpa16((char*)&sm[st][0][0][0] + (ci >> 2) * (LDT * 2) + (ci & 3) * 16, An + (size_t)ci * 8);
                cpa16((char*)&sm[st][1][0][0] + (ci >> 2) * (LDT * 2) + (ci & 3) * 16, Bn + (size_t)ci * 8);
            }
            CP_COMMIT();
            CP_WAIT(1);
        } else {
            CP_WAIT(0);
        }
        __syncthreads();

        uint32_t stg = sbase + (uint32_t)(kk & 1) * STAGE_BYTES;
#pragma unroll
        for (int ks = 0; ks < 2; ks++) {
            uint32_t kadj = (uint32_t)(ks * 32);   // 16 bf16 = 32 B
            uint32_t afr[4][4];
#pragma unroll
            for (int mt = 0; mt < 4; mt++) ldsm_x4(afr[mt], stg + a_off[mt] + kadj);
            uint32_t bfr[4][4];
#pragma unroll
            for (int ntp = 0; ntp < 4; ntp++) ldsm_x4(bfr[ntp], stg + b_off[ntp] + kadj);
#pragma unroll
            for (int mt = 0; mt < 4; mt++)
#pragma unroll
                for (int nt = 0; nt < 8; nt++)
                    mma16816(acc[mt][nt], afr[mt], &bfr[nt >> 1][(nt & 1) * 2]);
        }
        __syncthreads();
    }

    // epilogue: static-indexed float2 stores (no dynamic acc indexing -> no spills)
    float* Gp = g_G + (size_t)b * PQ * PQ;
#pragma unroll
    for (int mt = 0; mt < 4; mt++) {
        int row = m0 + warp_m * 64 + mt * 16 + g;
#pragma unroll
        for (int nt = 0; nt < 8; nt++) {
            int col = n0 + warp_n * 64 + nt * 8 + tig * 2;
            *(float2*)&Gp[(size_t)row * PQ + col]       = make_float2(acc[mt][nt][0], acc[mt][nt][1]);
            *(float2*)&Gp[(size_t)(row + 8) * PQ + col] = make_float2(acc[mt][nt][2], acc[mt][nt][3]);
        }
    }
}

// ---------------- K2: 9-tap diagonal sum + exp2 + out + column partials ----------------
__global__ __launch_bounds__(256) void k_sum9(float* __restrict__ out, int b) {
    int prow = blockIdx.y;
    int q    = blockIdx.x * 256 + threadIdx.x;
    int qy   = q >> 6, qx = q & 63;

    const float* __restrict__ Gp = g_G + (size_t)b * PQ * PQ;
    const float* __restrict__ cf = g_coef + b * PQ + prow * 64;

    const bool rvm = (prow > 0)  && (qy > 0);
    const bool rvp = (prow < 63) && (qy < 63);
    const bool qlf = (qx > 0), qrt = (qx < 63);

    const float* base = Gp + (size_t)(prow * 64) * PQ + q;
    float* orow = out + ((size_t)(b * PQ + prow * 64)) * PQ + q;
    float partial = 0.f;

#pragma unroll 8
    for (int px = 0; px < 64; px++) {
        bool lf = qlf && (px > 0);
        bool rt = qrt && (px < 63);
        float s = 0.f;
        if (rvm) {
            if (lf) s += __ldg(base - 65 * 4097);
            s += __ldg(base - 64 * 4097);
            if (rt) s += __ldg(base - 63 * 4097);
        }
        if (lf) s += __ldg(base - 4097);
        s += __ldg(base);
        if (rt) s += __ldg(base + 4097);
        if (rvp) {
            if (lf) s += __ldg(base + 63 * 4097);
            s += __ldg(base + 64 * 4097);
            if (rt) s += __ldg(base + 65 * 4097);
        }
        float e = fast_exp2(s * cf[px]);
        __stcs(orow, e);
        partial += e;
        base += PQ;
        orow += PQ;
    }
    g_partial[((size_t)(b * 64 + prow)) * PQ + q] = partial;
}

// ---------------- K2b: deterministic reduction of column partials ----------------
__global__ void k_colreduce(int b) {
    int q = blockIdx.x * 256 + threadIdx.x;
    const float* src = g_partial + (size_t)(b * 64) * PQ + q;
    float s = 0.f;
#pragma unroll 8
    for (int j = 0; j < 64; j++) s += src[(size_t)j * PQ];
    g_colsum[b * PQ + q] = s;
}

// ---------------- K3: normalize ----------------
__global__ void k_norm(float* __restrict__ out, int b) {
    size_t i4 = (size_t)blockIdx.x * 256 + threadIdx.x;   // within batch, PQ*PQ/4
    int p  = (int)(i4 >> 10);                              // 1024 float4 per row
    int c4 = (int)(i4 & 1023);
    size_t gi = (size_t)b * (PQ * (size_t)PQ / 4) + i4;

    float4 v  = __ldcs((const float4*)out + gi);
    float  m  = g_mm[p];
    float4 cs = ((const float4*)g_colsum)[b * 1024 + c4];
    v.x = m * v.x / cs.x;
    v.y = m * v.y / cs.y;
    v.z = m * v.z / cs.z;
    v.w = m * v.w / cs.w;
    __stcs((float4*)out + gi, v);
}

// ---------------- launch ----------------
extern "C" void kernel_launch(void* const* d_in, const int* in_sizes, int n_in,
                              void* d_out, int out_size) {
    const float* f    = (const float*)d_in[0];
    const float* bb   = (const float*)d_in[1];
    const float* mask = (const float*)d_in[2];
    float* out = (float*)d_out;

    k_split<<<dim3(PQ / 32, CH / 32, 2 * BATCH), dim3(32, 8)>>>(f, bb);
    k_ssq  <<<dim3(PQ / 256, BATCH), 256>>>(bb);
    k_prep <<<dim3(PQ / 256, BATCH), 256>>>(mask);

    // per-batch interleave: G (64MB) and out-slice (64MB) stay L2-resident
    // between producer and consumer kernels.
    for (int b = 0; b < BATCH; b++) {
        k_gemm_mma <<<dim3(PQ / 128, PQ / 128), 128>>>(b);
        k_sum9     <<<dim3(PQ / 256, 64), 256>>>(out, b);
        k_colreduce<<<PQ / 256, 256>>>(b);
        k_norm     <<<(unsigned)((PQ * (size_t)PQ / 4) / 256), 256>>>(out, b);
    }
}

// round 17
// speedup vs baseline: 1.2698x; 1.2395x over previous
#include <cuda_runtime.h>
#include <cuda_bf16.h>
#include <cstdint>

// Problem constants
#define BATCH 4
#define CH    128
#define HW    64
#define PQ    4096            // HW*HW
#define SCALE 10.0f
#define EPS_SUM 0.1152f       // 128*3*3*1e-4
#define LOG2E 1.4426950408889634f
#define KTOT  384             // split-bf16 packed K (ah|al|ah vs bh|bh|bl)
#define BKP   32              // bf16 K per pipeline stage
#define NKIT  (KTOT / BKP)    // 12 stages
#define LDT   40              // padded smem row length (bf16)
#define STAGE_BYTES (2 * 128 * LDT * 2)   // one stage (A+B)  = 20480 B
#define BREG_OFF    (128 * LDT * 2)       // B region within a stage = 10240 B
#define GGUARD 266368          // >= 65*4097 + 4096 + 65: covers every masked OOB tap

// ---------------- static scratch ----------------
__device__ float g_Gbuf[(size_t)BATCH * PQ * PQ + 2 * (size_t)GGUARD];
#define G_BASE (g_Gbuf + GGUARD)
__device__ float g_ssq[BATCH * PQ];
__device__ float g_coef[BATCH * PQ];
__device__ float g_mm[PQ];
__device__ float g_partial[BATCH * 64 * PQ];
__device__ float g_colsum[BATCH * PQ];
__device__ __nv_bfloat16 g_Apack[(size_t)BATCH * PQ * KTOT];  // from b: [p][ah|al|ah]
__device__ __nv_bfloat16 g_Bpack[(size_t)BATCH * PQ * KTOT];  // from f: [q][bh|bh|bl]

// ---------------- helpers ----------------
__device__ __forceinline__ uint32_t smem_u32(const void* p) {
    uint32_t a;
    asm("{ .reg .u64 t; cvta.to.shared.u64 t, %1; cvt.u32.u64 %0, t; }" : "=r"(a) : "l"(p));
    return a;
}
__device__ __forceinline__ void cpa16(void* dst, const void* src) {
    asm volatile("cp.async.cg.shared.global [%0], [%1], 16;"
                 :: "r"(smem_u32(dst)), "l"(src));
}
#define CP_COMMIT() asm volatile("cp.async.commit_group;" ::: "memory")
#define CP_WAIT(n)  asm volatile("cp.async.wait_group %0;" :: "n"(n) : "memory")

__device__ __forceinline__ void ldsm_x4(uint32_t* r, uint32_t addr) {
    asm volatile("ldmatrix.sync.aligned.m8n8.x4.shared.b16 {%0,%1,%2,%3}, [%4];"
                 : "=r"(r[0]), "=r"(r[1]), "=r"(r[2]), "=r"(r[3]) : "r"(addr));
}
__device__ __forceinline__ void mma16816(float* c, const uint32_t* a, const uint32_t* bfr) {
    asm volatile(
        "mma.sync.aligned.m16n8k16.row.col.f32.bf16.bf16.f32 "
        "{%0,%1,%2,%3}, {%4,%5,%6,%7}, {%8,%9}, {%0,%1,%2,%3};"
        : "+f"(c[0]), "+f"(c[1]), "+f"(c[2]), "+f"(c[3])
        : "r"(a[0]), "r"(a[1]), "r"(a[2]), "r"(a[3]), "r"(bfr[0]), "r"(bfr[1]));
}

// fast 2^t on the FMA pipe (degree-5, rel err ~2.4e-6)
__device__ __forceinline__ float fast_exp2(float t) {
    t = fminf(fmaxf(t, -120.0f), 120.0f);
    float fn = rintf(t);
    float f  = t - fn;
    float p  = 1.3333558e-3f;
    p = fmaf(p, f, 9.6181291e-3f);
    p = fmaf(p, f, 5.5504109e-2f);
    p = fmaf(p, f, 2.4022651e-1f);
    p = fmaf(p, f, 6.9314718e-1f);
    p = fmaf(p, f, 1.0f);
    int n = (int)fn;
    return p * __int_as_float((n + 127) << 23);
}

// ---------------- K-1: split fp32 -> packed bf16 hi/lo (transposed) ----------------
__global__ void k_split(const float* __restrict__ fin, const float* __restrict__ bin) {
    __shared__ float tile[32][33];
    int z = blockIdx.z;
    int isA = (z < BATCH);
    int b = isA ? z : z - BATCH;
    const float* src = (isA ? bin : fin) + (size_t)b * CH * PQ;
    __nv_bfloat16* dst = (isA ? g_Apack : g_Bpack) + (size_t)b * PQ * KTOT;

    int p0 = blockIdx.x * 32, c0 = blockIdx.y * 32;
    int tx = threadIdx.x, ty = threadIdx.y;   // (32, 8)
#pragma unroll
    for (int j = 0; j < 4; j++)
        tile[ty + 8 * j][tx] = src[(size_t)(c0 + ty + 8 * j) * PQ + p0 + tx];
    __syncthreads();
#pragma unroll
    for (int j = 0; j < 4; j++) {
        int r = ty + 8 * j;
        float a = tile[tx][r];
        __nv_bfloat16 hi = __float2bfloat16_rn(a);
        __nv_bfloat16 lo = __float2bfloat16_rn(a - __bfloat162float(hi));
        __nv_bfloat16* d = dst + (size_t)(p0 + r) * KTOT + c0 + tx;
        d[0]   = hi;
        d[128] = isA ? lo : hi;
        d[256] = isA ? hi : lo;
    }
}

// ---------------- K0a: ssq[b,p] = sum_c b[b,c,p]^2 ----------------
__global__ void k_ssq(const float* __restrict__ bin) {
    int p = blockIdx.x * 256 + threadIdx.x;
    int b = blockIdx.y;
    const float* src = bin + ((size_t)b * CH) * PQ + p;
    float s = 0.f;
#pragma unroll 8
    for (int c = 0; c < CH; c++) {
        float v = src[(size_t)c * PQ];
        s += v * v;
    }
    g_ssq[b * PQ + p] = s;
}

// ---------------- K0b: coef ----------------
__global__ void k_prep(const float* __restrict__ mask) {
    int p = blockIdx.x * 256 + threadIdx.x;
    int b = blockIdx.y;
    int py = p >> 6, px = p & 63;

    float s = EPS_SUM;
    bool masked = false;
#pragma unroll
    for (int dy = -1; dy <= 1; dy++) {
#pragma unroll
        for (int dx = -1; dx <= 1; dx++) {
            int yy = py + dy, xx = px + dx;
            if ((unsigned)yy < 64u && (unsigned)xx < 64u) {
                s += g_ssq[b * PQ + (yy << 6) + xx];
                if (mask[(size_t)(yy * 8) * 512 + xx * 8] != 0.0f) masked = true;
            }
        }
    }
    g_coef[b * PQ + p] = masked ? 0.0f : (SCALE * LOG2E / sqrtf(s));
    if (b == 0) g_mm[p] = masked ? 0.0f : 1.0f;
}

// ---------------- K1: HMMA bf16-split GEMM  Gt[p][q] = A.B (64x64 warp tile) -------
// CTA 128x128, K=384, BK=32, 128 thr = 4 warps (2 m x 2 n), warp tile 64x64.
// (R11 configuration: fastest measured GEMM, 168us)
__global__ __launch_bounds__(128, 2) void k_gemm_mma() {
    __shared__ __align__(16) __nv_bfloat16 sm[2][2][128][LDT];  // [stage][A/B][row][k]
    uint32_t sbase = smem_u32(&sm[0][0][0][0]);

    int tid = threadIdx.x;
    int wid = tid >> 5, lid = tid & 31;
    int g = lid >> 2, tig = lid & 3;
    int warp_m = wid & 1, warp_n = wid >> 1;

    int b  = blockIdx.z;
    int m0 = blockIdx.y * 128;   // p
    int n0 = blockIdx.x * 128;   // q
    const __nv_bfloat16* Ap = g_Apack + (size_t)b * PQ * KTOT;
    const __nv_bfloat16* Bp = g_Bpack + (size_t)b * PQ * KTOT;

    float acc[4][8][4];
#pragma unroll
    for (int mt = 0; mt < 4; mt++)
#pragma unroll
        for (int nt = 0; nt < 8; nt++)
#pragma unroll
            for (int i = 0; i < 4; i++) acc[mt][nt][i] = 0.f;

    // ldmatrix per-lane byte offsets within a stage
    uint32_t a_off[4];
#pragma unroll
    for (int mt = 0; mt < 4; mt++) {
        int row = warp_m * 64 + mt * 16 + (lid & 15);
        int kof = (lid >> 4) * 8;
        a_off[mt] = (uint32_t)((row * LDT + kof) * 2);
    }
    uint32_t b_off[4];
#pragma unroll
    for (int ntp = 0; ntp < 4; ntp++) {
        int row = warp_n * 64 + ntp * 16 + (lid & 7) + ((lid >> 4) << 3);
        int kof = ((lid >> 3) & 1) * 8;
        b_off[ntp] = (uint32_t)(BREG_OFF + (row * LDT + kof) * 2);
    }

    // stage fill: 128 rows x 4 x 16B chunks per operand; 4+4 chunks/thread (128 thr)
    int frow = tid >> 2;            // 0..31
    int fcu  = (tid & 3) * 8;
    const __nv_bfloat16* gA = Ap + (size_t)(m0 + frow) * KTOT + fcu;
    const __nv_bfloat16* gB = Bp + (size_t)(n0 + frow) * KTOT + fcu;

    // prefetch stage 0
#pragma unroll
    for (int h = 0; h < 4; h++) {
        cpa16(&sm[0][0][frow + h * 32][fcu], gA + (size_t)(h * 32) * KTOT);
        cpa16(&sm[0][1][frow + h * 32][fcu], gB + (size_t)(h * 32) * KTOT);
    }
    CP_COMMIT();

#pragma unroll 1
    for (int kk = 0; kk < NKIT; kk++) {
        if (kk + 1 < NKIT) {
            int st = (kk + 1) & 1, ko = (kk + 1) * BKP;
#pragma unroll
            for (int h = 0; h < 4; h++) {
                cpa16(&sm[st][0][frow + h * 32][fcu], gA + (size_t)(h * 32) * KTOT + ko);
                cpa16(&sm[st][1][frow + h * 32][fcu], gB + (size_t)(h * 32) * KTOT + ko);
            }
            CP_COMMIT();
            CP_WAIT(1);
        } else {
            CP_WAIT(0);
        }
        __syncthreads();

        uint32_t stg = sbase + (uint32_t)(kk & 1) * STAGE_BYTES;
#pragma unroll
        for (int ks = 0; ks < 2; ks++) {
            uint32_t kadj = (uint32_t)(ks * 32);   // 16 bf16 = 32 B
            uint32_t afr[4][4];
#pragma unroll
            for (int mt = 0; mt < 4; mt++) ldsm_x4(afr[mt], stg + a_off[mt] + kadj);
            uint32_t bfr[4][4];
#pragma unroll
            for (int ntp = 0; ntp < 4; ntp++) ldsm_x4(bfr[ntp], stg + b_off[ntp] + kadj);
#pragma unroll
            for (int mt = 0; mt < 4; mt++)
#pragma unroll
                for (int nt = 0; nt < 8; nt++)
                    mma16816(acc[mt][nt], afr[mt], &bfr[nt >> 1][(nt & 1) * 2]);
        }
        __syncthreads();
    }

    // epilogue: static-indexed float2 stores (no dynamic acc indexing -> no spills)
    float* Gp = G_BASE + (size_t)b * PQ * PQ;
#pragma unroll
    for (int mt = 0; mt < 4; mt++) {
        int row = m0 + warp_m * 64 + mt * 16 + g;
#pragma unroll
        for (int nt = 0; nt < 8; nt++) {
            int col = n0 + warp_n * 64 + nt * 8 + tig * 2;
            *(float2*)&Gp[(size_t)row * PQ + col]       = make_float2(acc[mt][nt][0], acc[mt][nt][1]);
            *(float2*)&Gp[(size_t)(row + 8) * PQ + col] = make_float2(acc[mt][nt][2], acc[mt][nt][3]);
        }
    }
}

// ---------------- K2: branch-free float2 9-tap sum + exp2 + partials ----------------
// Thread handles (q, q+1), q even. All taps loaded unconditionally (guarded array),
// validity applied via multiplicative masks. PL/PR are compile-time 0/1 literals for
// the peeled px=0 / px=63 iterations.
__device__ __forceinline__ void sum9_body(
    const float* __restrict__ base, float PL, float PR,
    float clx, float cry, float rm, float rp, float cf,
    float2* __restrict__ orow, float2& partial)
{
    const int D = 4097;
    float2 v0 = __ldg((const float2*)(base));
    float2 vm = __ldg((const float2*)(base - 64 * D));
    float2 vp = __ldg((const float2*)(base + 64 * D));
    float tm65x = __ldg(base - 65 * D), tm65y = __ldg(base - 65 * D + 1);
    float tm63x = __ldg(base - 63 * D), tm63y = __ldg(base - 63 * D + 1);
    float tm1x  = __ldg(base - D),      tm1y  = __ldg(base - D + 1);
    float tp1x  = __ldg(base + D),      tp1y  = __ldg(base + D + 1);
    float t63x  = __ldg(base + 63 * D), t63y  = __ldg(base + 63 * D + 1);
    float t65x  = __ldg(base + 65 * D), t65y  = __ldg(base + 65 * D + 1);

    float Lx = clx * PL, Ly = PL, Rx = PR, Ry = cry * PR;
    float sx = v0.x + Lx * tm1x + Rx * tp1x
             + rm * (vm.x + Lx * tm65x + Rx * tm63x)
             + rp * (vp.x + Lx * t63x + Rx * t65x);
    float sy = v0.y + Ly * tm1y + Ry * tp1y
             + rm * (vm.y + Ly * tm65y + Ry * tm63y)
             + rp * (vp.y + Ly * t63y + Ry * t65y);

    float2 e;
    e.x = fast_exp2(sx * cf);
    e.y = fast_exp2(sy * cf);
    __stcs(orow, e);
    partial.x += e.x;
    partial.y += e.y;
}

__global__ __launch_bounds__(256) void k_sum9(float* __restrict__ out) {
    int b    = blockIdx.z;
    int prow = blockIdx.y;
    int q    = blockIdx.x * 512 + threadIdx.x * 2;
    int qx   = q & 63, qy = q >> 6;

    float clx = (qx > 0)  ? 1.f : 0.f;   // x left mask (y left always valid)
    float cry = (qx < 62) ? 1.f : 0.f;   // y right mask (x right always valid)
    float rm  = (prow > 0  && qy > 0)  ? 1.f : 0.f;
    float rp  = (prow < 63 && qy < 63) ? 1.f : 0.f;

    const float* base = G_BASE + (size_t)b * PQ * PQ + (size_t)(prow * 64) * PQ + q;
    const float* cf = g_coef + b * PQ + prow * 64;
    float2* orow = (float2*)(out + ((size_t)(b * PQ + prow * 64)) * PQ + q);
    float2 partial = make_float2(0.f, 0.f);

    sum9_body(base, 0.f, 1.f, clx, cry, rm, rp, cf[0], orow, partial);
    base += PQ; orow += PQ / 2;
#pragma unroll 4
    for (int px = 1; px < 63; px++) {
        sum9_body(base, 1.f, 1.f, clx, cry, rm, rp, cf[px], orow, partial);
        base += PQ; orow += PQ / 2;
    }
    sum9_body(base, 1.f, 0.f, clx, cry, rm, rp, cf[63], orow, partial);

    *(float2*)&g_partial[((size_t)(b * 64 + prow)) * PQ + q] = partial;
}

// ---------------- K2b: deterministic reduction of column partials ----------------
__global__ void k_colreduce() {
    int q = blockIdx.x * 256 + threadIdx.x;
    int b = blockIdx.y;
    const float* src = g_partial + (size_t)(b * 64) * PQ + q;
    float s = 0.f;
#pragma unroll 8
    for (int j = 0; j < 64; j++) s += src[(size_t)j * PQ];
    g_colsum[b * PQ + q] = s;
}

// ---------------- K3: normalize ----------------
__global__ void k_norm(float* __restrict__ out) {
    size_t i4  = (size_t)blockIdx.x * 256 + threadIdx.x;
    size_t row = i4 >> 10;
    int p  = (int)(row & 4095);
    int b  = (int)(row >> 12);
    int c4 = (int)(i4 & 1023);

    float4 v  = __ldcs((const float4*)out + i4);
    float  m  = g_mm[p];
    float4 cs = ((const float4*)g_colsum)[b * 1024 + c4];
    v.x = m * v.x / cs.x;
    v.y = m * v.y / cs.y;
    v.z = m * v.z / cs.z;
    v.w = m * v.w / cs.w;
    __stcs((float4*)out + i4, v);
}

// ---------------- launch ----------------
extern "C" void kernel_launch(void* const* d_in, const int* in_sizes, int n_in,
                              void* d_out, int out_size) {
    const float* f    = (const float*)d_in[0];
    const float* bb   = (const float*)d_in[1];
    const float* mask = (const float*)d_in[2];
    float* out = (float*)d_out;

    k_split    <<<dim3(PQ / 32, CH / 32, 2 * BATCH), dim3(32, 8)>>>(f, bb);
    k_ssq      <<<dim3(PQ / 256, BATCH), 256>>>(bb);
    k_prep     <<<dim3(PQ / 256, BATCH), 256>>>(mask);
    k_gemm_mma <<<dim3(PQ / 128, PQ / 128, BATCH), 128>>>();
    k_sum9     <<<dim3(PQ / 512, 64, BATCH), 256>>>(out);
    k_colreduce<<<dim3(PQ / 256, BATCH), 256>>>();
    k_norm     <<<(unsigned)(((size_t)BATCH * PQ * PQ / 4) / 256), 256>>>(out);
}